// round 12
// baseline (speedup 1.0000x reference)
#include <cuda_runtime.h>
#include <cuda_fp16.h>
#include <cstdint>

#define B_   8
#define C_   64
#define H_   128
#define W_   128
#define CE_  576
#define P_   (H_*W_)
#define OUP_ 128
#define EPSF 1e-5f

typedef unsigned long long ull;

// ---- scratch (device globals; no runtime allocation allowed) ----
__device__ __half g_ah[(size_t)B_*CE_*P_];  // 151 MB: UNGATED relu(bn(dwconv)) fp16 [b][k][p]
__device__ __half g_wh[CE_*OUP_];           // fp16 weights, chunk-major [36][128 o][16 k]
__device__ float g_stats[B_*C_*2];          // sum, sumsq per (b,c)
__device__ float g_gate[B_*C_*4];           // G0, G1, A1, B1 per (b,c)
__device__ float g_ep[OUP_*2];              // conv BN folded: scale, shift per o

static __device__ __forceinline__ float tanhfast(float x) {
    float y;
    asm("tanh.approx.f32 %0, %1;" : "=f"(y) : "f"(x));
    return y;
}

#define PK2F(d,a,b)  asm("mov.b64 %0, {%1, %2};" : "=l"(d) : "f"(a), "f"(b))
#define UPK2F(a,b,d) asm("mov.b64 {%0, %1}, %2;" : "=f"(a), "=f"(b) : "l"(d))
#define MUL2(d,a,b)  asm("mul.rn.f32x2 %0, %1, %2;" : "=l"(d) : "l"(a), "l"(b))
#define FMA2(d,a,b,c) asm("fma.rn.f32x2 %0, %1, %2, %3;" : "=l"(d) : "l"(a), "l"(b), "l"(c))

// ---------------- k1: depthwise conv (packed f32x2) + BN + ReLU + fp16 store + stats ----------------
__global__ __launch_bounds__(256) void k1_gen(
    const float* __restrict__ x,  const float* __restrict__ gw,
    const float* __restrict__ bg, const float* __restrict__ bb,
    const float* __restrict__ bm, const float* __restrict__ bv)
{
    int t = threadIdx.x;
    int rowblk = blockIdx.x, c = blockIdx.y, b = blockIdx.z;
    __shared__ float sx[18*130];
    __shared__ __align__(8) float2 swv2[81], ssc2[9], ssh2[9];
    __shared__ float red[16];

    const float* xp = x + (size_t)(b*C_ + c)*P_;
    for (int idx = t; idx < 18*130; idx += 256) {
        int rr = idx / 130, cc = idx - rr*130;
        int gh = rowblk*16 + rr - 1, gwc = cc - 1;
        float v = 0.f;
        if ((unsigned)gh < (unsigned)H_ && (unsigned)gwc < (unsigned)W_)
            v = xp[gh*W_ + gwc];
        sx[idx] = v;
    }
    int ce0 = c*9;
    if (t < 81) {
        float w = gw[ce0*9 + t];
        swv2[t] = make_float2(w, w);
    }
    if (t < 9) {
        float g = bg[ce0+t];
        float sc = g / sqrtf(bv[ce0+t] + EPSF);
        float sh = bb[ce0+t] - bm[ce0+t]*sc;
        ssc2[t] = make_float2(sc, sc);
        ssh2[t] = make_float2(sh, sh);
    }
    __syncthreads();

    int r = t >> 4, c8 = (t & 15) * 8;
    ull P0[9], P1[9], P2[9];
    {
        float xs0[10], xs1[10], xs2[10];
        #pragma unroll
        for (int i = 0; i < 10; i++) {
            xs0[i] = sx[(r  )*130 + c8 + i];
            xs1[i] = sx[(r+1)*130 + c8 + i];
            xs2[i] = sx[(r+2)*130 + c8 + i];
        }
        #pragma unroll
        for (int s = 0; s < 9; s++) {
            PK2F(P0[s], xs0[s], xs0[s+1]);
            PK2F(P1[s], xs1[s], xs1[s+1]);
            PK2F(P2[s], xs2[s], xs2[s+1]);
        }
    }
    float lsum = 0.f, lsq = 0.f;
    int gh0 = rowblk*16 + r;
    #pragma unroll
    for (int j = 0; j < 9; j++) {
        const ull* wj = reinterpret_cast<const ull*>(&swv2[j*9]);
        ull w0=wj[0], w1=wj[1], w2=wj[2], w3=wj[3], w4=wj[4];
        ull w5=wj[5], w6=wj[6], w7=wj[7], w8=wj[8];
        ull scq = *reinterpret_cast<const ull*>(&ssc2[j]);
        ull shq = *reinterpret_cast<const ull*>(&ssh2[j]);
        ull acc2[4];
        #pragma unroll
        for (int p = 0; p < 4; p++) {
            ull a;
            MUL2(a, P0[2*p  ], w0);
            FMA2(a, P0[2*p+1], w1, a);
            FMA2(a, P0[2*p+2], w2, a);
            FMA2(a, P1[2*p  ], w3, a);
            FMA2(a, P1[2*p+1], w4, a);
            FMA2(a, P1[2*p+2], w5, a);
            FMA2(a, P2[2*p  ], w6, a);
            FMA2(a, P2[2*p+1], w7, a);
            FMA2(a, P2[2*p+2], w8, a);
            FMA2(a, a, scq, shq);   // BN
            acc2[p] = a;
        }
        uint4 u;
        unsigned* up = reinterpret_cast<unsigned*>(&u);
        #pragma unroll
        for (int p = 0; p < 4; p++) {
            float v0, v1;
            UPK2F(v0, v1, acc2[p]);
            float a0 = fmaxf(v0, 0.f), a1 = fmaxf(v1, 0.f);
            lsum += a0; lsq = fmaf(a0, a0, lsq);
            lsum += a1; lsq = fmaf(a1, a1, lsq);
            __half2 h = __floats2half2_rn(a0, a1);
            up[p] = *reinterpret_cast<unsigned*>(&h);
        }
        __half* op = g_ah + ((size_t)(b*CE_ + ce0 + j)*H_ + gh0)*W_ + c8;
        *reinterpret_cast<uint4*>(op) = u;
    }
    #pragma unroll
    for (int off = 16; off; off >>= 1) {
        lsum += __shfl_down_sync(0xffffffffu, lsum, off);
        lsq  += __shfl_down_sync(0xffffffffu, lsq , off);
    }
    int wid = t >> 5, lane = t & 31;
    if (lane == 0) { red[wid] = lsum; red[wid+8] = lsq; }
    __syncthreads();
    if (t == 0) {
        float s = 0.f, q = 0.f;
        #pragma unroll
        for (int i = 0; i < 8; i++) { s += red[i]; q += red[i+8]; }
        atomicAdd(&g_stats[(b*C_+c)*2+0], s);
        atomicAdd(&g_stats[(b*C_+c)*2+1], q);
    }
}

// ---------------- k2: fold gate params (tanh form) ----------------
__global__ void k2_gate(const float* __restrict__ gn_w, const float* __restrict__ gn_b,
    const float* __restrict__ cw, const float* __restrict__ cb,
    const float* __restrict__ sw, const float* __restrict__ sb,
    const float* __restrict__ wadd_p)
{
    int t = threadIdx.x;
    if (t >= B_*C_) return;
    int c = t & (C_-1), cg = c & 7;
    float s = g_stats[t*2], q = g_stats[t*2+1];
    const float N = (float)(9*P_);
    float mean = s / N;
    float var  = fmaxf(q / N - mean*mean, 0.f);
    float inv  = 1.f / sqrtf(var + EPSF);
    float wadd = *wadd_p;
    float tc = cw[cg]*mean + cb[cg];
    float gC = 1.f / (1.f + __expf(-tc));
    float alpha = sw[cg]*gn_w[cg]*inv;
    float beta  = sw[cg]*(gn_b[cg] - mean*inv*gn_w[cg]) + sb[cg];
    float w2 = 1.f - wadd;
    g_gate[t*4+0] = wadd*gC + 0.5f*w2;  // G0
    g_gate[t*4+1] = 0.5f*w2;            // G1
    g_gate[t*4+2] = 0.5f*alpha;         // A1
    g_gate[t*4+3] = 0.5f*beta;          // B1
}

// ---------------- k2b: zero stats + W fp16 chunk-major + fold conv BN ----------------
__global__ void k2b_prep(const float* __restrict__ cwv,
                         const float* __restrict__ g, const float* __restrict__ bb,
                         const float* __restrict__ m, const float* __restrict__ v)
{
    int idx = blockIdx.x*256 + threadIdx.x;
    if (idx < CE_*OUP_) {
        int o = idx / CE_, k = idx - o*CE_;
        g_wh[((size_t)(k >> 4)*OUP_ + o)*16 + (k & 15)] = __float2half_rn(cwv[idx]);
    }
    if (blockIdx.x == 0) {
        int i = threadIdx.x;
        g_stats[i] = 0.f; g_stats[i+256] = 0.f;
        g_stats[i+512] = 0.f; g_stats[i+768] = 0.f;
        if (i < OUP_) {
            float sc = g[i] / sqrtf(v[i] + EPSF);
            g_ep[i*2]   = sc;
            g_ep[i*2+1] = bb[i] - m[i]*sc;
        }
    }
}

// gate transform on 8 packed halves (fp32 math)
static __device__ __forceinline__ uint4 gate8(uint4 u, float4 gp) {
    __half2* h = reinterpret_cast<__half2*>(&u);
    #pragma unroll
    for (int i = 0; i < 4; i++) {
        float2 f = __half22float2(h[i]);
        float th0 = tanhfast(fmaf(gp.z, f.x, gp.w));
        float th1 = tanhfast(fmaf(gp.z, f.y, gp.w));
        h[i] = __floats2half2_rn(f.x * fmaf(gp.y, th0, gp.x),
                                 f.y * fmaf(gp.y, th1, gp.x));
    }
    return u;
}

// ---------------- k3: fp16 mma.sync GEMM, fused gate, LDG-prefetch 2-stage, 2 CTA/SM ----------------
#define LDSM4(r0,r1,r2,r3,addr) \
    asm volatile("ldmatrix.sync.aligned.m8n8.x4.shared.b16 {%0,%1,%2,%3}, [%4];" \
        : "=r"(r0),"=r"(r1),"=r"(r2),"=r"(r3) : "r"(addr))
#define LDSM4T(r0,r1,r2,r3,addr) \
    asm volatile("ldmatrix.sync.aligned.m8n8.x4.trans.shared.b16 {%0,%1,%2,%3}, [%4];" \
        : "=r"(r0),"=r"(r1),"=r"(r2),"=r"(r3) : "r"(addr))
#define MMA16816(c, a, b) \
    asm volatile("mma.sync.aligned.m16n8k16.row.col.f32.f16.f16.f32 " \
        "{%0,%1,%2,%3}, {%4,%5,%6,%7}, {%8,%9}, {%0,%1,%2,%3};" \
        : "+f"(c[0]),"+f"(c[1]),"+f"(c[2]),"+f"(c[3]) \
        : "r"(a[0]),"r"(a[1]),"r"(a[2]),"r"(a[3]), "r"(b[0]),"r"(b[1]))

static __device__ __forceinline__ uint32_t swoff(int row, int sel) {
    return (uint32_t)(row*32 + ((sel<<4) ^ ((row & 4) << 2)));
}

__global__ __launch_bounds__(256, 2) void k3_mma(float* __restrict__ out)
{
    __shared__ __align__(16) __half sW[2][2048];   // [stage][128m x 16k] swizzled
    __shared__ __align__(16) __half sB[2][2048];   // [stage][16k x 128pos] swizzled
    __shared__ __align__(16) float s_gp[256];

    int t = threadIdx.x, lane = t & 31, warp = t >> 5;
    int m_base = (warp >> 2) * 64;
    int n_base = (warp & 3) * 32;
    int b = blockIdx.y, pos0 = blockIdx.x * 128;

    s_gp[t] = g_gate[b*256 + t];
    const __half* aBase = g_ah + (size_t)b*CE_*P_ + pos0;

    float acc[4][4][4];
    #pragma unroll
    for (int i = 0; i < 4; i++)
        #pragma unroll
        for (int j = 0; j < 4; j++)
            #pragma unroll
            for (int k = 0; k < 4; k++) acc[i][j][k] = 0.f;

    uint32_t baseW = (uint32_t)__cvta_generic_to_shared(&sW[0][0]);
    uint32_t baseB = (uint32_t)__cvta_generic_to_shared(&sB[0][0]);

    // ldmatrix A offsets (non-trans, [m][k] rows of 32B)
    uint32_t offA = swoff(m_base + (lane & 15), lane >> 4);
    // ldmatrix B offsets (trans, [k][pos] rows of 256B, 16B-unit perm (c&8)|((c^k)&7))
    int gq = lane >> 3, rq = lane & 7;
    int kL = (gq & 1)*8 + rq;
    int cBb = (n_base >> 3) + (gq >> 1);
    // producer offsets
    int kb = t >> 4, chb = t & 15;
    uint32_t bsm = (uint32_t)kb*256 + (uint32_t)(((chb & 8) | ((chb ^ kb) & 7)) << 4);
    int wrow = t >> 1, wsel = t & 1;
    uint32_t wst = swoff(wrow, wsel);
    const __half* wPtr = g_wh + ((size_t)wrow*16) + wsel*8;

    // ---- prologue: chunk 0 ----
    {
        uint4 wv = *reinterpret_cast<const uint4*>(wPtr);
        uint4 bv = *reinterpret_cast<const uint4*>(aBase + (size_t)kb*P_ + chb*8);
        __syncthreads();  // s_gp ready
        *reinterpret_cast<uint4*>(reinterpret_cast<char*>(&sW[0][0]) + wst) = wv;
        float4 gp = reinterpret_cast<const float4*>(s_gp)[kb/9];
        *reinterpret_cast<uint4*>(reinterpret_cast<char*>(&sB[0][0]) + bsm) = gate8(bv, gp);
    }
    __syncthreads();

    for (int kc = 0; kc < 36; kc++) {
        int cur = kc & 1, nxt = cur ^ 1;
        uint4 wv, bv;
        if (kc < 35) {
            int k0 = (kc+1)*16;
            wv = *reinterpret_cast<const uint4*>(wPtr + (size_t)(kc+1)*OUP_*16);
            bv = *reinterpret_cast<const uint4*>(aBase + (size_t)(k0+kb)*P_ + chb*8);
        }
        // MMA on current stage
        {
            uint32_t aW = baseW + cur*4096 + offA;
            uint32_t aB2 = baseB + cur*4096;
            uint32_t afr[4][4], bfr[4][2];
            #pragma unroll
            for (int fm = 0; fm < 4; fm++)
                LDSM4(afr[fm][0], afr[fm][1], afr[fm][2], afr[fm][3], aW + fm*512);
            #pragma unroll
            for (int pr = 0; pr < 2; pr++) {
                uint32_t r0, r1, r2, r3;
                int cc = cBb + pr*2;
                int s16 = (cc & 8) | ((cc ^ kL) & 7);
                uint32_t off = (uint32_t)kL*256 + (uint32_t)s16*16;
                LDSM4T(r0, r1, r2, r3, aB2 + off);
                bfr[2*pr][0] = r0; bfr[2*pr][1] = r1;
                bfr[2*pr+1][0] = r2; bfr[2*pr+1][1] = r3;
            }
            #pragma unroll
            for (int fm = 0; fm < 4; fm++)
                #pragma unroll
                for (int fn = 0; fn < 4; fn++)
                    MMA16816(acc[fm][fn], afr[fm], bfr[fn]);
        }
        // gate + store next chunk
        if (kc < 35) {
            int k0 = (kc+1)*16;
            *reinterpret_cast<uint4*>(reinterpret_cast<char*>(&sW[0][0]) + nxt*4096 + wst) = wv;
            float4 gp = reinterpret_cast<const float4*>(s_gp)[(k0+kb)/9];
            *reinterpret_cast<uint4*>(reinterpret_cast<char*>(&sB[0][0]) + nxt*4096 + bsm) =
                gate8(bv, gp);
        }
        __syncthreads();
    }

    // epilogue: BN + SiLU + store
    int g = lane >> 2, tc4 = lane & 3;
    #pragma unroll
    for (int fm = 0; fm < 4; fm++) {
        int r0 = m_base + 16*fm + g, r1 = r0 + 8;
        float sc0 = g_ep[r0*2], sh0 = g_ep[r0*2+1];
        float sc1 = g_ep[r1*2], sh1 = g_ep[r1*2+1];
        float* o0 = out + ((size_t)b*OUP_ + r0)*P_ + pos0 + n_base + 2*tc4;
        float* o1 = out + ((size_t)b*OUP_ + r1)*P_ + pos0 + n_base + 2*tc4;
        #pragma unroll
        for (int fn = 0; fn < 4; fn++) {
            float z0 = fmaf(acc[fm][fn][0], sc0, sh0);
            float z1 = fmaf(acc[fm][fn][1], sc0, sh0);
            float z2 = fmaf(acc[fm][fn][2], sc1, sh1);
            float z3 = fmaf(acc[fm][fn][3], sc1, sh1);
            float2 v0 = make_float2(z0/(1.f+__expf(-z0)), z1/(1.f+__expf(-z1)));
            float2 v1 = make_float2(z2/(1.f+__expf(-z2)), z3/(1.f+__expf(-z3)));
            *reinterpret_cast<float2*>(o0 + 8*fn) = v0;
            *reinterpret_cast<float2*>(o1 + 8*fn) = v1;
        }
    }
}

extern "C" void kernel_launch(void* const* d_in, const int* in_sizes, int n_in,
                              void* d_out, int out_size)
{
    const float* x      = (const float*)d_in[0];
    const float* gen_w  = (const float*)d_in[1];
    const float* bg     = (const float*)d_in[2];
    const float* bb     = (const float*)d_in[3];
    const float* bm     = (const float*)d_in[4];
    const float* bv     = (const float*)d_in[5];
    const float* gn_w   = (const float*)d_in[6];
    const float* gn_b   = (const float*)d_in[7];
    const float* cw     = (const float*)d_in[8];
    const float* cb     = (const float*)d_in[9];
    const float* sw     = (const float*)d_in[10];
    const float* sb     = (const float*)d_in[11];
    const float* wadd   = (const float*)d_in[12];
    const float* conv_w = (const float*)d_in[13];
    const float* cbg    = (const float*)d_in[14];
    const float* cbb    = (const float*)d_in[15];
    const float* cbm    = (const float*)d_in[16];
    const float* cbv    = (const float*)d_in[17];
    float* out = (float*)d_out;

    k2b_prep<<<(CE_*OUP_ + 255)/256, 256>>>(conv_w, cbg, cbb, cbm, cbv);  // also zeros stats
    k1_gen<<<dim3(8, C_, B_), 256>>>(x, gen_w, bg, bb, bm, bv);
    k2_gate<<<1, 512>>>(gn_w, gn_b, cw, cb, sw, sb, wadd);
    k3_mma<<<dim3(P_/128, B_), 256>>>(out);
}

// round 13
// speedup vs baseline: 1.1982x; 1.1982x over previous
#include <cuda_runtime.h>
#include <cuda_fp16.h>
#include <cstdint>

#define B_   8
#define C_   64
#define H_   128
#define W_   128
#define CE_  576
#define P_   (H_*W_)
#define OUP_ 128
#define EPSF 1e-5f

typedef unsigned long long ull;

// ---- scratch (device globals; no runtime allocation allowed) ----
__device__ __half g_ah[(size_t)B_*CE_*P_];  // 151 MB: UNGATED relu(bn(dwconv)) fp16 [b][k][p]
__device__ __half g_wh[CE_*OUP_];           // fp16 weights, chunk-major [36][128 o][16 k]
__device__ float g_stats[B_*C_*2];          // sum, sumsq per (b,c)
__device__ float g_gate[B_*C_*4];           // G0, G1, A1, B1 per (b,c)
__device__ float g_ep[OUP_*2];              // conv BN folded: scale, shift per o

static __device__ __forceinline__ float tanhfast(float x) {
    float y;
    asm("tanh.approx.f32 %0, %1;" : "=f"(y) : "f"(x));
    return y;
}

#define PK2F(d,a,b)  asm("mov.b64 %0, {%1, %2};" : "=l"(d) : "f"(a), "f"(b))
#define UPK2F(a,b,d) asm("mov.b64 {%0, %1}, %2;" : "=f"(a), "=f"(b) : "l"(d))
#define MUL2(d,a,b)  asm("mul.rn.f32x2 %0, %1, %2;" : "=l"(d) : "l"(a), "l"(b))
#define FMA2(d,a,b,c) asm("fma.rn.f32x2 %0, %1, %2, %3;" : "=l"(d) : "l"(a), "l"(b), "l"(c))

// ---------------- k1: depthwise conv (packed f32x2) + BN + ReLU + fp16 store + stats ----------------
__global__ __launch_bounds__(256) void k1_gen(
    const float* __restrict__ x,  const float* __restrict__ gw,
    const float* __restrict__ bg, const float* __restrict__ bb,
    const float* __restrict__ bm, const float* __restrict__ bv)
{
    int t = threadIdx.x;
    int rowblk = blockIdx.x, c = blockIdx.y, b = blockIdx.z;
    __shared__ float sx[18*130];
    __shared__ __align__(8) float2 swv2[81], ssc2[9], ssh2[9];
    __shared__ float red[16];

    const float* xp = x + (size_t)(b*C_ + c)*P_;
    for (int idx = t; idx < 18*130; idx += 256) {
        int rr = idx / 130, cc = idx - rr*130;
        int gh = rowblk*16 + rr - 1, gwc = cc - 1;
        float v = 0.f;
        if ((unsigned)gh < (unsigned)H_ && (unsigned)gwc < (unsigned)W_)
            v = xp[gh*W_ + gwc];
        sx[idx] = v;
    }
    int ce0 = c*9;
    if (t < 81) {
        float w = gw[ce0*9 + t];
        swv2[t] = make_float2(w, w);
    }
    if (t < 9) {
        float g = bg[ce0+t];
        float sc = g / sqrtf(bv[ce0+t] + EPSF);
        float sh = bb[ce0+t] - bm[ce0+t]*sc;
        ssc2[t] = make_float2(sc, sc);
        ssh2[t] = make_float2(sh, sh);
    }
    __syncthreads();

    int r = t >> 4, c8 = (t & 15) * 8;
    ull P0[9], P1[9], P2[9];
    {
        float xs0[10], xs1[10], xs2[10];
        #pragma unroll
        for (int i = 0; i < 10; i++) {
            xs0[i] = sx[(r  )*130 + c8 + i];
            xs1[i] = sx[(r+1)*130 + c8 + i];
            xs2[i] = sx[(r+2)*130 + c8 + i];
        }
        #pragma unroll
        for (int s = 0; s < 9; s++) {
            PK2F(P0[s], xs0[s], xs0[s+1]);
            PK2F(P1[s], xs1[s], xs1[s+1]);
            PK2F(P2[s], xs2[s], xs2[s+1]);
        }
    }
    float lsum = 0.f, lsq = 0.f;
    int gh0 = rowblk*16 + r;
    #pragma unroll
    for (int j = 0; j < 9; j++) {
        const ull* wj = reinterpret_cast<const ull*>(&swv2[j*9]);
        ull w0=wj[0], w1=wj[1], w2=wj[2], w3=wj[3], w4=wj[4];
        ull w5=wj[5], w6=wj[6], w7=wj[7], w8=wj[8];
        ull scq = *reinterpret_cast<const ull*>(&ssc2[j]);
        ull shq = *reinterpret_cast<const ull*>(&ssh2[j]);
        ull acc2[4];
        #pragma unroll
        for (int p = 0; p < 4; p++) {
            ull a;
            MUL2(a, P0[2*p  ], w0);
            FMA2(a, P0[2*p+1], w1, a);
            FMA2(a, P0[2*p+2], w2, a);
            FMA2(a, P1[2*p  ], w3, a);
            FMA2(a, P1[2*p+1], w4, a);
            FMA2(a, P1[2*p+2], w5, a);
            FMA2(a, P2[2*p  ], w6, a);
            FMA2(a, P2[2*p+1], w7, a);
            FMA2(a, P2[2*p+2], w8, a);
            FMA2(a, a, scq, shq);   // BN
            acc2[p] = a;
        }
        uint4 u;
        unsigned* up = reinterpret_cast<unsigned*>(&u);
        #pragma unroll
        for (int p = 0; p < 4; p++) {
            float v0, v1;
            UPK2F(v0, v1, acc2[p]);
            float a0 = fmaxf(v0, 0.f), a1 = fmaxf(v1, 0.f);
            lsum += a0; lsq = fmaf(a0, a0, lsq);
            lsum += a1; lsq = fmaf(a1, a1, lsq);
            __half2 h = __floats2half2_rn(a0, a1);
            up[p] = *reinterpret_cast<unsigned*>(&h);
        }
        __half* op = g_ah + ((size_t)(b*CE_ + ce0 + j)*H_ + gh0)*W_ + c8;
        *reinterpret_cast<uint4*>(op) = u;
    }
    #pragma unroll
    for (int off = 16; off; off >>= 1) {
        lsum += __shfl_down_sync(0xffffffffu, lsum, off);
        lsq  += __shfl_down_sync(0xffffffffu, lsq , off);
    }
    int wid = t >> 5, lane = t & 31;
    if (lane == 0) { red[wid] = lsum; red[wid+8] = lsq; }
    __syncthreads();
    if (t == 0) {
        float s = 0.f, q = 0.f;
        #pragma unroll
        for (int i = 0; i < 8; i++) { s += red[i]; q += red[i+8]; }
        atomicAdd(&g_stats[(b*C_+c)*2+0], s);
        atomicAdd(&g_stats[(b*C_+c)*2+1], q);
    }
}

// ---------------- k2: fold gate params (tanh form) ----------------
__global__ void k2_gate(const float* __restrict__ gn_w, const float* __restrict__ gn_b,
    const float* __restrict__ cw, const float* __restrict__ cb,
    const float* __restrict__ sw, const float* __restrict__ sb,
    const float* __restrict__ wadd_p)
{
    int t = threadIdx.x;
    if (t >= B_*C_) return;
    int c = t & (C_-1), cg = c & 7;
    float s = g_stats[t*2], q = g_stats[t*2+1];
    const float N = (float)(9*P_);
    float mean = s / N;
    float var  = fmaxf(q / N - mean*mean, 0.f);
    float inv  = 1.f / sqrtf(var + EPSF);
    float wadd = *wadd_p;
    float tc = cw[cg]*mean + cb[cg];
    float gC = 1.f / (1.f + __expf(-tc));
    float alpha = sw[cg]*gn_w[cg]*inv;
    float beta  = sw[cg]*(gn_b[cg] - mean*inv*gn_w[cg]) + sb[cg];
    float w2 = 1.f - wadd;
    g_gate[t*4+0] = wadd*gC + 0.5f*w2;  // G0
    g_gate[t*4+1] = 0.5f*w2;            // G1
    g_gate[t*4+2] = 0.5f*alpha;         // A1
    g_gate[t*4+3] = 0.5f*beta;          // B1
}

// ---------------- k2b: zero stats + W fp16 chunk-major + fold conv BN ----------------
__global__ void k2b_prep(const float* __restrict__ cwv,
                         const float* __restrict__ g, const float* __restrict__ bb,
                         const float* __restrict__ m, const float* __restrict__ v)
{
    int idx = blockIdx.x*256 + threadIdx.x;
    if (idx < CE_*OUP_) {
        int o = idx / CE_, k = idx - o*CE_;
        g_wh[((size_t)(k >> 4)*OUP_ + o)*16 + (k & 15)] = __float2half_rn(cwv[idx]);
    }
    if (blockIdx.x == 0) {
        int i = threadIdx.x;
        g_stats[i] = 0.f; g_stats[i+256] = 0.f;
        g_stats[i+512] = 0.f; g_stats[i+768] = 0.f;
        if (i < OUP_) {
            float sc = g[i] / sqrtf(v[i] + EPSF);
            g_ep[i*2]   = sc;
            g_ep[i*2+1] = bb[i] - m[i]*sc;
        }
    }
}

// gate transform on 8 packed halves (fp32 math)
static __device__ __forceinline__ uint4 gate8(uint4 u, float4 gp) {
    __half2* h = reinterpret_cast<__half2*>(&u);
    #pragma unroll
    for (int i = 0; i < 4; i++) {
        float2 f = __half22float2(h[i]);
        float th0 = tanhfast(fmaf(gp.z, f.x, gp.w));
        float th1 = tanhfast(fmaf(gp.z, f.y, gp.w));
        h[i] = __floats2half2_rn(f.x * fmaf(gp.y, th0, gp.x),
                                 f.y * fmaf(gp.y, th1, gp.x));
    }
    return u;
}

// ---------------- k3: fp16 mma.sync GEMM, cp.async 6-stage + in-smem gate ----------------
#define LDSM4(r0,r1,r2,r3,addr) \
    asm volatile("ldmatrix.sync.aligned.m8n8.x4.shared.b16 {%0,%1,%2,%3}, [%4];" \
        : "=r"(r0),"=r"(r1),"=r"(r2),"=r"(r3) : "r"(addr))
#define LDSM4T(r0,r1,r2,r3,addr) \
    asm volatile("ldmatrix.sync.aligned.m8n8.x4.trans.shared.b16 {%0,%1,%2,%3}, [%4];" \
        : "=r"(r0),"=r"(r1),"=r"(r2),"=r"(r3) : "r"(addr))
#define MMA16816(c, a, b) \
    asm volatile("mma.sync.aligned.m16n8k16.row.col.f32.f16.f16.f32 " \
        "{%0,%1,%2,%3}, {%4,%5,%6,%7}, {%8,%9}, {%0,%1,%2,%3};" \
        : "+f"(c[0]),"+f"(c[1]),"+f"(c[2]),"+f"(c[3]) \
        : "r"(a[0]),"r"(a[1]),"r"(a[2]),"r"(a[3]), "r"(b[0]),"r"(b[1]))
#define CP16(dst, src) \
    asm volatile("cp.async.cg.shared.global [%0], [%1], 16;" :: "r"(dst), "l"(src))
#define CPCOMMIT() asm volatile("cp.async.commit_group;" ::: "memory")
#define CPWAIT4()  asm volatile("cp.async.wait_group 4;" ::: "memory")

static __device__ __forceinline__ uint32_t swoff(int row, int sel) {
    return (uint32_t)(row*32 + ((sel<<4) ^ ((row & 4) << 2)));
}

#define K3_STAGE 8192           // W 4KB + B 4KB per stage
#define K3_GP    49152          // gate params after 6 stages
#define K3_DYN   (49152 + 1024)

__global__ __launch_bounds__(256, 2) void k3_mma(float* __restrict__ out)
{
    extern __shared__ __align__(16) char dyn[];

    int t = threadIdx.x, lane = t & 31, warp = t >> 5;
    int m_base = (warp >> 2) * 64;
    int n_base = (warp & 3) * 32;
    int b = blockIdx.y, pos0 = blockIdx.x * 128;

    reinterpret_cast<float*>(dyn + K3_GP)[t] = g_gate[b*256 + t];
    const float4* gpArr = reinterpret_cast<const float4*>(dyn + K3_GP);
    const __half* aBase = g_ah + (size_t)b*CE_*P_ + pos0;

    float acc[4][4][4];
    #pragma unroll
    for (int i = 0; i < 4; i++)
        #pragma unroll
        for (int j = 0; j < 4; j++)
            #pragma unroll
            for (int k = 0; k < 4; k++) acc[i][j][k] = 0.f;

    uint32_t stBase = (uint32_t)__cvta_generic_to_shared(dyn);

    // ldmatrix A offsets (non-trans, [m][k] rows of 32B)
    uint32_t offA = swoff(m_base + (lane & 15), lane >> 4);
    // ldmatrix B offsets (trans, [k][pos] rows of 256B, 16B-unit perm (c&8)|((c^k)&7))
    int gq = lane >> 3, rq = lane & 7;
    int kL = (gq & 1)*8 + rq;
    int cBb = (n_base >> 3) + (gq >> 1);
    // producer offsets
    int kb = t >> 4, chb = t & 15;
    uint32_t bsm = (uint32_t)kb*256 + (uint32_t)(((chb & 8) | ((chb ^ kb) & 7)) << 4);
    int wrow = t >> 1, wsel = t & 1;
    uint32_t wst = swoff(wrow, wsel);
    const __half* wPtr = g_wh + ((size_t)wrow*16) + wsel*8;

    auto issue = [&](int kc) {
        int st = kc % 6;
        CP16(stBase + st*K3_STAGE + wst, wPtr + (size_t)kc*OUP_*16);
        CP16(stBase + st*K3_STAGE + 4096 + bsm, aBase + (size_t)(kc*16 + kb)*P_ + chb*8);
        CPCOMMIT();
    };
    issue(0); issue(1); issue(2); issue(3); issue(4);

    for (int kc = 0; kc < 36; kc++) {
        int cur = kc % 6;
        CPWAIT4();
        __syncthreads();           // stage cur landed; prior ldmatrix reads done
        if (kc < 31) issue(kc + 5);
        else CPCOMMIT();
        // in-smem gate of B half of stage cur (conflict-free 128-bit RMW)
        {
            uint4* bp = reinterpret_cast<uint4*>(dyn + cur*K3_STAGE + 4096 + bsm);
            float4 gp = gpArr[(kc*16 + kb) / 9];
            *bp = gate8(*bp, gp);
        }
        __syncthreads();           // gated data visible
        uint32_t aW = stBase + cur*K3_STAGE + offA;
        uint32_t aB2 = stBase + cur*K3_STAGE + 4096;
        uint32_t afr[4][4], bfr[4][2];
        #pragma unroll
        for (int fm = 0; fm < 4; fm++)
            LDSM4(afr[fm][0], afr[fm][1], afr[fm][2], afr[fm][3], aW + fm*512);
        #pragma unroll
        for (int pr = 0; pr < 2; pr++) {
            uint32_t r0, r1, r2, r3;
            int cc = cBb + pr*2;
            int s16 = (cc & 8) | ((cc ^ kL) & 7);
            uint32_t off = (uint32_t)kL*256 + (uint32_t)s16*16;
            LDSM4T(r0, r1, r2, r3, aB2 + off);
            bfr[2*pr][0] = r0; bfr[2*pr][1] = r1;
            bfr[2*pr+1][0] = r2; bfr[2*pr+1][1] = r3;
        }
        #pragma unroll
        for (int fm = 0; fm < 4; fm++)
            #pragma unroll
            for (int fn = 0; fn < 4; fn++)
                MMA16816(acc[fm][fn], afr[fm], bfr[fn]);
    }

    // epilogue: BN + SiLU + store
    int g = lane >> 2, tc4 = lane & 3;
    #pragma unroll
    for (int fm = 0; fm < 4; fm++) {
        int r0 = m_base + 16*fm + g, r1 = r0 + 8;
        float sc0 = g_ep[r0*2], sh0 = g_ep[r0*2+1];
        float sc1 = g_ep[r1*2], sh1 = g_ep[r1*2+1];
        float* o0 = out + ((size_t)b*OUP_ + r0)*P_ + pos0 + n_base + 2*tc4;
        float* o1 = out + ((size_t)b*OUP_ + r1)*P_ + pos0 + n_base + 2*tc4;
        #pragma unroll
        for (int fn = 0; fn < 4; fn++) {
            float z0 = fmaf(acc[fm][fn][0], sc0, sh0);
            float z1 = fmaf(acc[fm][fn][1], sc0, sh0);
            float z2 = fmaf(acc[fm][fn][2], sc1, sh1);
            float z3 = fmaf(acc[fm][fn][3], sc1, sh1);
            float2 v0 = make_float2(z0/(1.f+__expf(-z0)), z1/(1.f+__expf(-z1)));
            float2 v1 = make_float2(z2/(1.f+__expf(-z2)), z3/(1.f+__expf(-z3)));
            *reinterpret_cast<float2*>(o0 + 8*fn) = v0;
            *reinterpret_cast<float2*>(o1 + 8*fn) = v1;
        }
    }
}

extern "C" void kernel_launch(void* const* d_in, const int* in_sizes, int n_in,
                              void* d_out, int out_size)
{
    const float* x      = (const float*)d_in[0];
    const float* gen_w  = (const float*)d_in[1];
    const float* bg     = (const float*)d_in[2];
    const float* bb     = (const float*)d_in[3];
    const float* bm     = (const float*)d_in[4];
    const float* bv     = (const float*)d_in[5];
    const float* gn_w   = (const float*)d_in[6];
    const float* gn_b   = (const float*)d_in[7];
    const float* cw     = (const float*)d_in[8];
    const float* cb     = (const float*)d_in[9];
    const float* sw     = (const float*)d_in[10];
    const float* sb     = (const float*)d_in[11];
    const float* wadd   = (const float*)d_in[12];
    const float* conv_w = (const float*)d_in[13];
    const float* cbg    = (const float*)d_in[14];
    const float* cbb    = (const float*)d_in[15];
    const float* cbm    = (const float*)d_in[16];
    const float* cbv    = (const float*)d_in[17];
    float* out = (float*)d_out;

    cudaFuncSetAttribute(k3_mma, cudaFuncAttributeMaxDynamicSharedMemorySize, K3_DYN);

    k2b_prep<<<(CE_*OUP_ + 255)/256, 256>>>(conv_w, cbg, cbb, cbm, cbv);  // also zeros stats
    k1_gen<<<dim3(8, C_, B_), 256>>>(x, gen_w, bg, bb, bm, bv);
    k2_gate<<<1, 512>>>(gn_w, gn_b, cw, cb, sw, sb, wadd);
    k3_mma<<<dim3(P_/128, B_), 256, K3_DYN>>>(out);
}

// round 14
// speedup vs baseline: 1.2515x; 1.0445x over previous
#include <cuda_runtime.h>
#include <cuda_fp16.h>
#include <cstdint>

#define B_   8
#define C_   64
#define H_   128
#define W_   128
#define CE_  576
#define P_   (H_*W_)
#define OUP_ 128
#define EPSF 1e-5f

typedef unsigned long long ull;

// ---- scratch (device globals; no runtime allocation allowed) ----
__device__ __half g_ah[(size_t)B_*CE_*P_];  // 151 MB: UNGATED relu(bn(dwconv)) fp16 [b][k][p]
__device__ __half g_wh[CE_*OUP_];           // fp16 weights, chunk-major [36][128 o][16 k]
__device__ float g_stats[B_*C_*2];          // sum, sumsq per (b,c)
__device__ float g_gate[B_*C_*4];           // G0, G1, A1, B1 per (b,c)
__device__ float g_ep[OUP_*2];              // conv BN folded: scale, shift per o

static __device__ __forceinline__ float tanhfast(float x) {
    float y;
    asm("tanh.approx.f32 %0, %1;" : "=f"(y) : "f"(x));
    return y;
}

#define PK2F(d,a,b)  asm("mov.b64 %0, {%1, %2};" : "=l"(d) : "f"(a), "f"(b))
#define UPK2F(a,b,d) asm("mov.b64 {%0, %1}, %2;" : "=f"(a), "=f"(b) : "l"(d))
#define MUL2(d,a,b)  asm("mul.rn.f32x2 %0, %1, %2;" : "=l"(d) : "l"(a), "l"(b))
#define FMA2(d,a,b,c) asm("fma.rn.f32x2 %0, %1, %2, %3;" : "=l"(d) : "l"(a), "l"(b), "l"(c))

// ---------------- k1: depthwise conv (packed f32x2) + BN + ReLU + fp16 store + stats ----------------
__global__ __launch_bounds__(256) void k1_gen(
    const float* __restrict__ x,  const float* __restrict__ gw,
    const float* __restrict__ bg, const float* __restrict__ bb,
    const float* __restrict__ bm, const float* __restrict__ bv)
{
    int t = threadIdx.x;
    int rowblk = blockIdx.x, c = blockIdx.y, b = blockIdx.z;
    __shared__ float sx[18*130];
    __shared__ __align__(8) float2 swv2[81], ssc2[9], ssh2[9];
    __shared__ float red[16];

    const float* xp = x + (size_t)(b*C_ + c)*P_;
    for (int idx = t; idx < 18*130; idx += 256) {
        int rr = idx / 130, cc = idx - rr*130;
        int gh = rowblk*16 + rr - 1, gwc = cc - 1;
        float v = 0.f;
        if ((unsigned)gh < (unsigned)H_ && (unsigned)gwc < (unsigned)W_)
            v = xp[gh*W_ + gwc];
        sx[idx] = v;
    }
    int ce0 = c*9;
    if (t < 81) {
        float w = gw[ce0*9 + t];
        swv2[t] = make_float2(w, w);
    }
    if (t < 9) {
        float g = bg[ce0+t];
        float sc = g / sqrtf(bv[ce0+t] + EPSF);
        float sh = bb[ce0+t] - bm[ce0+t]*sc;
        ssc2[t] = make_float2(sc, sc);
        ssh2[t] = make_float2(sh, sh);
    }
    __syncthreads();

    int r = t >> 4, c8 = (t & 15) * 8;
    ull P0[9], P1[9], P2[9];
    {
        float xs0[10], xs1[10], xs2[10];
        #pragma unroll
        for (int i = 0; i < 10; i++) {
            xs0[i] = sx[(r  )*130 + c8 + i];
            xs1[i] = sx[(r+1)*130 + c8 + i];
            xs2[i] = sx[(r+2)*130 + c8 + i];
        }
        #pragma unroll
        for (int s = 0; s < 9; s++) {
            PK2F(P0[s], xs0[s], xs0[s+1]);
            PK2F(P1[s], xs1[s], xs1[s+1]);
            PK2F(P2[s], xs2[s], xs2[s+1]);
        }
    }
    float lsum = 0.f, lsq = 0.f;
    int gh0 = rowblk*16 + r;
    #pragma unroll
    for (int j = 0; j < 9; j++) {
        const ull* wj = reinterpret_cast<const ull*>(&swv2[j*9]);
        ull w0=wj[0], w1=wj[1], w2=wj[2], w3=wj[3], w4=wj[4];
        ull w5=wj[5], w6=wj[6], w7=wj[7], w8=wj[8];
        ull scq = *reinterpret_cast<const ull*>(&ssc2[j]);
        ull shq = *reinterpret_cast<const ull*>(&ssh2[j]);
        ull acc2[4];
        #pragma unroll
        for (int p = 0; p < 4; p++) {
            ull a;
            MUL2(a, P0[2*p  ], w0);
            FMA2(a, P0[2*p+1], w1, a);
            FMA2(a, P0[2*p+2], w2, a);
            FMA2(a, P1[2*p  ], w3, a);
            FMA2(a, P1[2*p+1], w4, a);
            FMA2(a, P1[2*p+2], w5, a);
            FMA2(a, P2[2*p  ], w6, a);
            FMA2(a, P2[2*p+1], w7, a);
            FMA2(a, P2[2*p+2], w8, a);
            FMA2(a, a, scq, shq);   // BN
            acc2[p] = a;
        }
        uint4 u;
        unsigned* up = reinterpret_cast<unsigned*>(&u);
        #pragma unroll
        for (int p = 0; p < 4; p++) {
            float v0, v1;
            UPK2F(v0, v1, acc2[p]);
            float a0 = fmaxf(v0, 0.f), a1 = fmaxf(v1, 0.f);
            lsum += a0; lsq = fmaf(a0, a0, lsq);
            lsum += a1; lsq = fmaf(a1, a1, lsq);
            __half2 h = __floats2half2_rn(a0, a1);
            up[p] = *reinterpret_cast<unsigned*>(&h);
        }
        __half* op = g_ah + ((size_t)(b*CE_ + ce0 + j)*H_ + gh0)*W_ + c8;
        *reinterpret_cast<uint4*>(op) = u;
    }
    #pragma unroll
    for (int off = 16; off; off >>= 1) {
        lsum += __shfl_down_sync(0xffffffffu, lsum, off);
        lsq  += __shfl_down_sync(0xffffffffu, lsq , off);
    }
    int wid = t >> 5, lane = t & 31;
    if (lane == 0) { red[wid] = lsum; red[wid+8] = lsq; }
    __syncthreads();
    if (t == 0) {
        float s = 0.f, q = 0.f;
        #pragma unroll
        for (int i = 0; i < 8; i++) { s += red[i]; q += red[i+8]; }
        atomicAdd(&g_stats[(b*C_+c)*2+0], s);
        atomicAdd(&g_stats[(b*C_+c)*2+1], q);
    }
}

// ---------------- k2: fold gate params (tanh form) ----------------
__global__ void k2_gate(const float* __restrict__ gn_w, const float* __restrict__ gn_b,
    const float* __restrict__ cw, const float* __restrict__ cb,
    const float* __restrict__ sw, const float* __restrict__ sb,
    const float* __restrict__ wadd_p)
{
    int t = threadIdx.x;
    if (t >= B_*C_) return;
    int c = t & (C_-1), cg = c & 7;
    float s = g_stats[t*2], q = g_stats[t*2+1];
    const float N = (float)(9*P_);
    float mean = s / N;
    float var  = fmaxf(q / N - mean*mean, 0.f);
    float inv  = 1.f / sqrtf(var + EPSF);
    float wadd = *wadd_p;
    float tc = cw[cg]*mean + cb[cg];
    float gC = 1.f / (1.f + __expf(-tc));
    float alpha = sw[cg]*gn_w[cg]*inv;
    float beta  = sw[cg]*(gn_b[cg] - mean*inv*gn_w[cg]) + sb[cg];
    float w2 = 1.f - wadd;
    g_gate[t*4+0] = wadd*gC + 0.5f*w2;  // G0
    g_gate[t*4+1] = 0.5f*w2;            // G1
    g_gate[t*4+2] = 0.5f*alpha;         // A1
    g_gate[t*4+3] = 0.5f*beta;          // B1
}

// ---------------- k2b: zero stats + W fp16 chunk-major + fold conv BN ----------------
__global__ void k2b_prep(const float* __restrict__ cwv,
                         const float* __restrict__ g, const float* __restrict__ bb,
                         const float* __restrict__ m, const float* __restrict__ v)
{
    int idx = blockIdx.x*256 + threadIdx.x;
    if (idx < CE_*OUP_) {
        int o = idx / CE_, k = idx - o*CE_;
        g_wh[((size_t)(k >> 4)*OUP_ + o)*16 + (k & 15)] = __float2half_rn(cwv[idx]);
    }
    if (blockIdx.x == 0) {
        int i = threadIdx.x;
        g_stats[i] = 0.f; g_stats[i+256] = 0.f;
        g_stats[i+512] = 0.f; g_stats[i+768] = 0.f;
        if (i < OUP_) {
            float sc = g[i] / sqrtf(v[i] + EPSF);
            g_ep[i*2]   = sc;
            g_ep[i*2+1] = bb[i] - m[i]*sc;
        }
    }
}

// gate transform on 8 packed halves (fp32 math)
static __device__ __forceinline__ uint4 gate8(uint4 u, float4 gp) {
    __half2* h = reinterpret_cast<__half2*>(&u);
    #pragma unroll
    for (int i = 0; i < 4; i++) {
        float2 f = __half22float2(h[i]);
        float th0 = tanhfast(fmaf(gp.z, f.x, gp.w));
        float th1 = tanhfast(fmaf(gp.z, f.y, gp.w));
        h[i] = __floats2half2_rn(f.x * fmaf(gp.y, th0, gp.x),
                                 f.y * fmaf(gp.y, th1, gp.x));
    }
    return u;
}

// ---------------- k3: fp16 mma.sync GEMM, 8-stage cp.async, thread-local early gate, 1 sync/chunk ----------------
#define LDSM4(r0,r1,r2,r3,addr) \
    asm volatile("ldmatrix.sync.aligned.m8n8.x4.shared.b16 {%0,%1,%2,%3}, [%4];" \
        : "=r"(r0),"=r"(r1),"=r"(r2),"=r"(r3) : "r"(addr))
#define LDSM4T(r0,r1,r2,r3,addr) \
    asm volatile("ldmatrix.sync.aligned.m8n8.x4.trans.shared.b16 {%0,%1,%2,%3}, [%4];" \
        : "=r"(r0),"=r"(r1),"=r"(r2),"=r"(r3) : "r"(addr))
#define MMA16816(c, a, b) \
    asm volatile("mma.sync.aligned.m16n8k16.row.col.f32.f16.f16.f32 " \
        "{%0,%1,%2,%3}, {%4,%5,%6,%7}, {%8,%9}, {%0,%1,%2,%3};" \
        : "+f"(c[0]),"+f"(c[1]),"+f"(c[2]),"+f"(c[3]) \
        : "r"(a[0]),"r"(a[1]),"r"(a[2]),"r"(a[3]), "r"(b[0]),"r"(b[1]))
#define CP16(dst, src) \
    asm volatile("cp.async.cg.shared.global [%0], [%1], 16;" :: "r"(dst), "l"(src))
#define CPCOMMIT() asm volatile("cp.async.commit_group;" ::: "memory")
#define CPWAIT5()  asm volatile("cp.async.wait_group 5;" ::: "memory")
#define CPWAIT6()  asm volatile("cp.async.wait_group 6;" ::: "memory")

static __device__ __forceinline__ uint32_t swoff(int row, int sel) {
    return (uint32_t)(row*32 + ((sel<<4) ^ ((row & 4) << 2)));
}

#define K3_STAGE 8192           // W 4KB + B 4KB per stage
#define K3_NST   8
#define K3_GP    (K3_NST*K3_STAGE)   // gate params after stages
#define K3_DYN   (K3_GP + 1024)

__global__ __launch_bounds__(256, 2) void k3_mma(float* __restrict__ out)
{
    extern __shared__ __align__(16) char dyn[];

    int t = threadIdx.x, lane = t & 31, warp = t >> 5;
    int m_base = (warp >> 2) * 64;
    int n_base = (warp & 3) * 32;
    int b = blockIdx.y, pos0 = blockIdx.x * 128;

    reinterpret_cast<float*>(dyn + K3_GP)[t] = g_gate[b*256 + t];
    const float4* gpArr = reinterpret_cast<const float4*>(dyn + K3_GP);
    const __half* aBase = g_ah + (size_t)b*CE_*P_ + pos0;

    float acc[4][4][4];
    #pragma unroll
    for (int i = 0; i < 4; i++)
        #pragma unroll
        for (int j = 0; j < 4; j++)
            #pragma unroll
            for (int k = 0; k < 4; k++) acc[i][j][k] = 0.f;

    uint32_t stBase = (uint32_t)__cvta_generic_to_shared(dyn);

    uint32_t offA = swoff(m_base + (lane & 15), lane >> 4);
    int gq = lane >> 3, rq = lane & 7;
    int kL = (gq & 1)*8 + rq;
    int cBb = (n_base >> 3) + (gq >> 1);
    // producer offsets
    int kb = t >> 4, chb = t & 15;
    uint32_t bsm = (uint32_t)kb*256 + (uint32_t)(((chb & 8) | ((chb ^ kb) & 7)) << 4);
    int wrow = t >> 1, wsel = t & 1;
    uint32_t wst = swoff(wrow, wsel);
    const __half* wPtr = g_wh + ((size_t)wrow*16) + wsel*8;

    auto issue = [&](int kc) {
        int st = kc & (K3_NST-1);
        CP16(stBase + st*K3_STAGE + wst, wPtr + (size_t)kc*OUP_*16);
        CP16(stBase + st*K3_STAGE + 4096 + bsm, aBase + (size_t)(kc*16 + kb)*P_ + chb*8);
        CPCOMMIT();
    };
    // thread-local gate of own B region of stage for chunk kc
    auto gateStage = [&](int kc) {
        int st = kc & (K3_NST-1);
        uint4* bp = reinterpret_cast<uint4*>(dyn + st*K3_STAGE + 4096 + bsm);
        float4 gp = gpArr[(kc*16 + kb) / 9];
        *bp = gate8(*bp, gp);
    };

    issue(0); issue(1); issue(2); issue(3); issue(4); issue(5); issue(6);
    CPWAIT6();          // stage 0 landed (this thread's own copies visible)
    __syncthreads();    // gp table published
    gateStage(0);

    for (int kc = 0; kc < 36; kc++) {
        if (kc < 35) {
            CPWAIT5();           // stages <= kc+1 landed
            gateStage(kc + 1);   // thread-local RMW, no barrier needed
        }
        __syncthreads();         // gates of stage kc (prev iter) + consumption of stage kc-1 drained
        if (kc < 29) issue(kc + 7);
        else CPCOMMIT();
        int cur = kc & (K3_NST-1);
        uint32_t aW = stBase + cur*K3_STAGE + offA;
        uint32_t aB2 = stBase + cur*K3_STAGE + 4096;
        uint32_t afr[4][4], bfr[4][2];
        #pragma unroll
        for (int fm = 0; fm < 4; fm++)
            LDSM4(afr[fm][0], afr[fm][1], afr[fm][2], afr[fm][3], aW + fm*512);
        #pragma unroll
        for (int pr = 0; pr < 2; pr++) {
            uint32_t r0, r1, r2, r3;
            int cc = cBb + pr*2;
            int s16 = (cc & 8) | ((cc ^ kL) & 7);
            uint32_t off = (uint32_t)kL*256 + (uint32_t)s16*16;
            LDSM4T(r0, r1, r2, r3, aB2 + off);
            bfr[2*pr][0] = r0; bfr[2*pr][1] = r1;
            bfr[2*pr+1][0] = r2; bfr[2*pr+1][1] = r3;
        }
        #pragma unroll
        for (int fm = 0; fm < 4; fm++)
            #pragma unroll
            for (int fn = 0; fn < 4; fn++)
                MMA16816(acc[fm][fn], afr[fm], bfr[fn]);
    }

    // epilogue: BN + SiLU + store
    int g = lane >> 2, tc4 = lane & 3;
    #pragma unroll
    for (int fm = 0; fm < 4; fm++) {
        int r0 = m_base + 16*fm + g, r1 = r0 + 8;
        float sc0 = g_ep[r0*2], sh0 = g_ep[r0*2+1];
        float sc1 = g_ep[r1*2], sh1 = g_ep[r1*2+1];
        float* o0 = out + ((size_t)b*OUP_ + r0)*P_ + pos0 + n_base + 2*tc4;
        float* o1 = out + ((size_t)b*OUP_ + r1)*P_ + pos0 + n_base + 2*tc4;
        #pragma unroll
        for (int fn = 0; fn < 4; fn++) {
            float z0 = fmaf(acc[fm][fn][0], sc0, sh0);
            float z1 = fmaf(acc[fm][fn][1], sc0, sh0);
            float z2 = fmaf(acc[fm][fn][2], sc1, sh1);
            float z3 = fmaf(acc[fm][fn][3], sc1, sh1);
            float2 v0 = make_float2(z0/(1.f+__expf(-z0)), z1/(1.f+__expf(-z1)));
            float2 v1 = make_float2(z2/(1.f+__expf(-z2)), z3/(1.f+__expf(-z3)));
            *reinterpret_cast<float2*>(o0 + 8*fn) = v0;
            *reinterpret_cast<float2*>(o1 + 8*fn) = v1;
        }
    }
}

extern "C" void kernel_launch(void* const* d_in, const int* in_sizes, int n_in,
                              void* d_out, int out_size)
{
    const float* x      = (const float*)d_in[0];
    const float* gen_w  = (const float*)d_in[1];
    const float* bg     = (const float*)d_in[2];
    const float* bb     = (const float*)d_in[3];
    const float* bm     = (const float*)d_in[4];
    const float* bv     = (const float*)d_in[5];
    const float* gn_w   = (const float*)d_in[6];
    const float* gn_b   = (const float*)d_in[7];
    const float* cw     = (const float*)d_in[8];
    const float* cb     = (const float*)d_in[9];
    const float* sw     = (const float*)d_in[10];
    const float* sb     = (const float*)d_in[11];
    const float* wadd   = (const float*)d_in[12];
    const float* conv_w = (const float*)d_in[13];
    const float* cbg    = (const float*)d_in[14];
    const float* cbb    = (const float*)d_in[15];
    const float* cbm    = (const float*)d_in[16];
    const float* cbv    = (const float*)d_in[17];
    float* out = (float*)d_out;

    cudaFuncSetAttribute(k3_mma, cudaFuncAttributeMaxDynamicSharedMemorySize, K3_DYN);

    k2b_prep<<<(CE_*OUP_ + 255)/256, 256>>>(conv_w, cbg, cbb, cbm, cbv);  // also zeros stats
    k1_gen<<<dim3(8, C_, B_), 256>>>(x, gen_w, bg, bb, bm, bv);
    k2_gate<<<1, 512>>>(gn_w, gn_b, cw, cb, sw, sb, wadd);
    k3_mma<<<dim3(P_/128, B_), 256, K3_DYN>>>(out);
}

// round 15
// speedup vs baseline: 1.2677x; 1.0130x over previous
#include <cuda_runtime.h>
#include <cuda_fp16.h>
#include <cstdint>

#define B_   8
#define C_   64
#define H_   128
#define W_   128
#define CE_  576
#define P_   (H_*W_)
#define OUP_ 128
#define EPSF 1e-5f

typedef unsigned long long ull;

// ---- scratch (device globals; no runtime allocation allowed) ----
__device__ __half g_ah[(size_t)B_*CE_*P_];  // 151 MB: UNGATED relu(bn(dwconv)) fp16 [b][k][p]
__device__ __half g_wh[CE_*OUP_];           // fp16 weights, chunk-major [36][128 o][16 k]
__device__ float g_stats[B_*C_*2];          // sum, sumsq per (b,c)
__device__ float g_gate[B_*C_*4];           // G0, G1, A1, B1 per (b,c)
__device__ float g_ep[OUP_*2];              // conv BN folded: scale, shift per o

static __device__ __forceinline__ float tanhfast(float x) {
    float y;
    asm("tanh.approx.f32 %0, %1;" : "=f"(y) : "f"(x));
    return y;
}

#define PK2F(d,a,b)  asm("mov.b64 %0, {%1, %2};" : "=l"(d) : "f"(a), "f"(b))
#define UPK2F(a,b,d) asm("mov.b64 {%0, %1}, %2;" : "=f"(a), "=f"(b) : "l"(d))
#define MUL2(d,a,b)  asm("mul.rn.f32x2 %0, %1, %2;" : "=l"(d) : "l"(a), "l"(b))
#define FMA2(d,a,b,c) asm("fma.rn.f32x2 %0, %1, %2, %3;" : "=l"(d) : "l"(a), "l"(b), "l"(c))

// ---------------- k1: depthwise conv (packed f32x2) + BN + ReLU + fp16 store + stats ----------------
__global__ __launch_bounds__(256) void k1_gen(
    const float* __restrict__ x,  const float* __restrict__ gw,
    const float* __restrict__ bg, const float* __restrict__ bb,
    const float* __restrict__ bm, const float* __restrict__ bv)
{
    int t = threadIdx.x;
    int rowblk = blockIdx.x, c = blockIdx.y, b = blockIdx.z;
    __shared__ float sx[18*130];
    __shared__ __align__(8) float2 swv2[81], ssc2[9], ssh2[9];
    __shared__ float red[16];

    const float* xp = x + (size_t)(b*C_ + c)*P_;
    for (int idx = t; idx < 18*130; idx += 256) {
        int rr = idx / 130, cc = idx - rr*130;
        int gh = rowblk*16 + rr - 1, gwc = cc - 1;
        float v = 0.f;
        if ((unsigned)gh < (unsigned)H_ && (unsigned)gwc < (unsigned)W_)
            v = xp[gh*W_ + gwc];
        sx[idx] = v;
    }
    int ce0 = c*9;
    if (t < 81) {
        float w = gw[ce0*9 + t];
        swv2[t] = make_float2(w, w);
    }
    if (t < 9) {
        float g = bg[ce0+t];
        float sc = g / sqrtf(bv[ce0+t] + EPSF);
        float sh = bb[ce0+t] - bm[ce0+t]*sc;
        ssc2[t] = make_float2(sc, sc);
        ssh2[t] = make_float2(sh, sh);
    }
    __syncthreads();

    int r = t >> 4, c8 = (t & 15) * 8;
    ull P0[9], P1[9], P2[9];
    {
        float xs0[10], xs1[10], xs2[10];
        #pragma unroll
        for (int i = 0; i < 10; i++) {
            xs0[i] = sx[(r  )*130 + c8 + i];
            xs1[i] = sx[(r+1)*130 + c8 + i];
            xs2[i] = sx[(r+2)*130 + c8 + i];
        }
        #pragma unroll
        for (int s = 0; s < 9; s++) {
            PK2F(P0[s], xs0[s], xs0[s+1]);
            PK2F(P1[s], xs1[s], xs1[s+1]);
            PK2F(P2[s], xs2[s], xs2[s+1]);
        }
    }
    float lsum = 0.f, lsq = 0.f;
    int gh0 = rowblk*16 + r;
    #pragma unroll
    for (int j = 0; j < 9; j++) {
        const ull* wj = reinterpret_cast<const ull*>(&swv2[j*9]);
        ull w0=wj[0], w1=wj[1], w2=wj[2], w3=wj[3], w4=wj[4];
        ull w5=wj[5], w6=wj[6], w7=wj[7], w8=wj[8];
        ull scq = *reinterpret_cast<const ull*>(&ssc2[j]);
        ull shq = *reinterpret_cast<const ull*>(&ssh2[j]);
        ull acc2[4];
        #pragma unroll
        for (int p = 0; p < 4; p++) {
            ull a;
            MUL2(a, P0[2*p  ], w0);
            FMA2(a, P0[2*p+1], w1, a);
            FMA2(a, P0[2*p+2], w2, a);
            FMA2(a, P1[2*p  ], w3, a);
            FMA2(a, P1[2*p+1], w4, a);
            FMA2(a, P1[2*p+2], w5, a);
            FMA2(a, P2[2*p  ], w6, a);
            FMA2(a, P2[2*p+1], w7, a);
            FMA2(a, P2[2*p+2], w8, a);
            FMA2(a, a, scq, shq);   // BN
            acc2[p] = a;
        }
        uint4 u;
        unsigned* up = reinterpret_cast<unsigned*>(&u);
        #pragma unroll
        for (int p = 0; p < 4; p++) {
            float v0, v1;
            UPK2F(v0, v1, acc2[p]);
            float a0 = fmaxf(v0, 0.f), a1 = fmaxf(v1, 0.f);
            lsum += a0; lsq = fmaf(a0, a0, lsq);
            lsum += a1; lsq = fmaf(a1, a1, lsq);
            __half2 h = __floats2half2_rn(a0, a1);
            up[p] = *reinterpret_cast<unsigned*>(&h);
        }
        __half* op = g_ah + ((size_t)(b*CE_ + ce0 + j)*H_ + gh0)*W_ + c8;
        *reinterpret_cast<uint4*>(op) = u;
    }
    #pragma unroll
    for (int off = 16; off; off >>= 1) {
        lsum += __shfl_down_sync(0xffffffffu, lsum, off);
        lsq  += __shfl_down_sync(0xffffffffu, lsq , off);
    }
    int wid = t >> 5, lane = t & 31;
    if (lane == 0) { red[wid] = lsum; red[wid+8] = lsq; }
    __syncthreads();
    if (t == 0) {
        float s = 0.f, q = 0.f;
        #pragma unroll
        for (int i = 0; i < 8; i++) { s += red[i]; q += red[i+8]; }
        atomicAdd(&g_stats[(b*C_+c)*2+0], s);
        atomicAdd(&g_stats[(b*C_+c)*2+1], q);
    }
}

// ---------------- k2: fold gate params (tanh form) ----------------
__global__ void k2_gate(const float* __restrict__ gn_w, const float* __restrict__ gn_b,
    const float* __restrict__ cw, const float* __restrict__ cb,
    const float* __restrict__ sw, const float* __restrict__ sb,
    const float* __restrict__ wadd_p)
{
    int t = threadIdx.x;
    if (t >= B_*C_) return;
    int c = t & (C_-1), cg = c & 7;
    float s = g_stats[t*2], q = g_stats[t*2+1];
    const float N = (float)(9*P_);
    float mean = s / N;
    float var  = fmaxf(q / N - mean*mean, 0.f);
    float inv  = 1.f / sqrtf(var + EPSF);
    float wadd = *wadd_p;
    float tc = cw[cg]*mean + cb[cg];
    float gC = 1.f / (1.f + __expf(-tc));
    float alpha = sw[cg]*gn_w[cg]*inv;
    float beta  = sw[cg]*(gn_b[cg] - mean*inv*gn_w[cg]) + sb[cg];
    float w2 = 1.f - wadd;
    g_gate[t*4+0] = wadd*gC + 0.5f*w2;  // G0
    g_gate[t*4+1] = 0.5f*w2;            // G1
    g_gate[t*4+2] = 0.5f*alpha;         // A1
    g_gate[t*4+3] = 0.5f*beta;          // B1
}

// ---------------- k2b: zero stats + W fp16 chunk-major + fold conv BN ----------------
__global__ void k2b_prep(const float* __restrict__ cwv,
                         const float* __restrict__ g, const float* __restrict__ bb,
                         const float* __restrict__ m, const float* __restrict__ v)
{
    int idx = blockIdx.x*256 + threadIdx.x;
    if (idx < CE_*OUP_) {
        int o = idx / CE_, k = idx - o*CE_;
        g_wh[((size_t)(k >> 4)*OUP_ + o)*16 + (k & 15)] = __float2half_rn(cwv[idx]);
    }
    if (blockIdx.x == 0) {
        int i = threadIdx.x;
        g_stats[i] = 0.f; g_stats[i+256] = 0.f;
        g_stats[i+512] = 0.f; g_stats[i+768] = 0.f;
        if (i < OUP_) {
            float sc = g[i] / sqrtf(v[i] + EPSF);
            g_ep[i*2]   = sc;
            g_ep[i*2+1] = bb[i] - m[i]*sc;
        }
    }
}

// fp16 gate transform on 8 packed halves: a * (G0 + G1*tanh(A1*a + B1))
// gp packed as uint4 {A1A1, B1B1, G1G1, G0G0}
static __device__ __forceinline__ uint4 gate8h(uint4 u, uint4 gp) {
    __half2 A1 = *reinterpret_cast<__half2*>(&gp.x);
    __half2 B1 = *reinterpret_cast<__half2*>(&gp.y);
    __half2 G1 = *reinterpret_cast<__half2*>(&gp.z);
    __half2 G0 = *reinterpret_cast<__half2*>(&gp.w);
    __half2* h = reinterpret_cast<__half2*>(&u);
    #pragma unroll
    for (int i = 0; i < 4; i++) {
        __half2 a = h[i];
        __half2 tt = __hfma2(A1, a, B1);
        uint32_t th;
        asm("tanh.approx.f16x2 %0, %1;" : "=r"(th) : "r"(*reinterpret_cast<uint32_t*>(&tt)));
        __half2 g = __hfma2(G1, *reinterpret_cast<__half2*>(&th), G0);
        h[i] = __hmul2(a, g);
    }
    return u;
}

// ---------------- k3: fp16 mma.sync GEMM, 8-stage cp.async, fp16 thread-local gate ----------------
#define LDSM4(r0,r1,r2,r3,addr) \
    asm volatile("ldmatrix.sync.aligned.m8n8.x4.shared.b16 {%0,%1,%2,%3}, [%4];" \
        : "=r"(r0),"=r"(r1),"=r"(r2),"=r"(r3) : "r"(addr))
#define LDSM4T(r0,r1,r2,r3,addr) \
    asm volatile("ldmatrix.sync.aligned.m8n8.x4.trans.shared.b16 {%0,%1,%2,%3}, [%4];" \
        : "=r"(r0),"=r"(r1),"=r"(r2),"=r"(r3) : "r"(addr))
#define MMA16816(c, a, b) \
    asm volatile("mma.sync.aligned.m16n8k16.row.col.f32.f16.f16.f32 " \
        "{%0,%1,%2,%3}, {%4,%5,%6,%7}, {%8,%9}, {%0,%1,%2,%3};" \
        : "+f"(c[0]),"+f"(c[1]),"+f"(c[2]),"+f"(c[3]) \
        : "r"(a[0]),"r"(a[1]),"r"(a[2]),"r"(a[3]), "r"(b[0]),"r"(b[1]))
#define CP16(dst, src) \
    asm volatile("cp.async.cg.shared.global [%0], [%1], 16;" :: "r"(dst), "l"(src))
#define CPCOMMIT() asm volatile("cp.async.commit_group;" ::: "memory")
#define CPWAIT5()  asm volatile("cp.async.wait_group 5;" ::: "memory")
#define CPWAIT6()  asm volatile("cp.async.wait_group 6;" ::: "memory")

static __device__ __forceinline__ uint32_t swoff(int row, int sel) {
    return (uint32_t)(row*32 + ((sel<<4) ^ ((row & 4) << 2)));
}

#define K3_STAGE 8192           // W 4KB + B 4KB per stage
#define K3_NST   8
#define K3_GP    (K3_NST*K3_STAGE)   // half2 gate table after stages (64 x 16B)
#define K3_DYN   (K3_GP + 1024)

__global__ __launch_bounds__(256, 2) void k3_mma(float* __restrict__ out)
{
    extern __shared__ __align__(16) char dyn[];

    int t = threadIdx.x, lane = t & 31, warp = t >> 5;
    int m_base = (warp >> 2) * 64;
    int n_base = (warp & 3) * 32;
    int b = blockIdx.y, pos0 = blockIdx.x * 128;

    if (t < 64) {
        float4 gp = reinterpret_cast<const float4*>(g_gate)[b*C_ + t];
        __half2 a1 = __float2half2_rn(gp.z);
        __half2 b1 = __float2half2_rn(gp.w);
        __half2 g1 = __float2half2_rn(gp.y);
        __half2 g0 = __float2half2_rn(gp.x);
        uint4 pk;
        pk.x = *reinterpret_cast<uint32_t*>(&a1);
        pk.y = *reinterpret_cast<uint32_t*>(&b1);
        pk.z = *reinterpret_cast<uint32_t*>(&g1);
        pk.w = *reinterpret_cast<uint32_t*>(&g0);
        reinterpret_cast<uint4*>(dyn + K3_GP)[t] = pk;
    }
    const uint4* gpArr = reinterpret_cast<const uint4*>(dyn + K3_GP);
    const __half* aBase = g_ah + (size_t)b*CE_*P_ + pos0;

    float acc[4][4][4];
    #pragma unroll
    for (int i = 0; i < 4; i++)
        #pragma unroll
        for (int j = 0; j < 4; j++)
            #pragma unroll
            for (int k = 0; k < 4; k++) acc[i][j][k] = 0.f;

    uint32_t stBase = (uint32_t)__cvta_generic_to_shared(dyn);

    uint32_t offA = swoff(m_base + (lane & 15), lane >> 4);
    int gq = lane >> 3, rq = lane & 7;
    int kL = (gq & 1)*8 + rq;
    int cBb = (n_base >> 3) + (gq >> 1);
    // producer offsets
    int kb = t >> 4, chb = t & 15;
    uint32_t bsm = (uint32_t)kb*256 + (uint32_t)(((chb & 8) | ((chb ^ kb) & 7)) << 4);
    int wrow = t >> 1, wsel = t & 1;
    uint32_t wst = swoff(wrow, wsel);
    const __half* wPtr = g_wh + ((size_t)wrow*16) + wsel*8;

    auto issue = [&](int kc) {
        int st = kc & (K3_NST-1);
        CP16(stBase + st*K3_STAGE + wst, wPtr + (size_t)kc*OUP_*16);
        CP16(stBase + st*K3_STAGE + 4096 + bsm, aBase + (size_t)(kc*16 + kb)*P_ + chb*8);
        CPCOMMIT();
    };
    auto gateStage = [&](int kc) {
        int st = kc & (K3_NST-1);
        uint4* bp = reinterpret_cast<uint4*>(dyn + st*K3_STAGE + 4096 + bsm);
        *bp = gate8h(*bp, gpArr[(kc*16 + kb) / 9]);
    };

    issue(0); issue(1); issue(2); issue(3); issue(4); issue(5); issue(6);
    CPWAIT6();          // stage 0 landed (this thread's own copies visible)
    __syncthreads();    // gp table published
    gateStage(0);

    for (int kc = 0; kc < 36; kc++) {
        if (kc < 35) {
            CPWAIT5();           // stages <= kc+1 landed
            gateStage(kc + 1);   // thread-local RMW, no barrier needed
        }
        __syncthreads();         // gates of stage kc + consumption of stage kc-1 drained
        if (kc < 29) issue(kc + 7);
        else CPCOMMIT();
        int cur = kc & (K3_NST-1);
        uint32_t aW = stBase + cur*K3_STAGE + offA;
        uint32_t aB2 = stBase + cur*K3_STAGE + 4096;
        uint32_t afr[4][4], bfr[4][2];
        #pragma unroll
        for (int fm = 0; fm < 4; fm++)
            LDSM4(afr[fm][0], afr[fm][1], afr[fm][2], afr[fm][3], aW + fm*512);
        #pragma unroll
        for (int pr = 0; pr < 2; pr++) {
            uint32_t r0, r1, r2, r3;
            int cc = cBb + pr*2;
            int s16 = (cc & 8) | ((cc ^ kL) & 7);
            uint32_t off = (uint32_t)kL*256 + (uint32_t)s16*16;
            LDSM4T(r0, r1, r2, r3, aB2 + off);
            bfr[2*pr][0] = r0; bfr[2*pr][1] = r1;
            bfr[2*pr+1][0] = r2; bfr[2*pr+1][1] = r3;
        }
        #pragma unroll
        for (int fm = 0; fm < 4; fm++)
            #pragma unroll
            for (int fn = 0; fn < 4; fn++)
                MMA16816(acc[fm][fn], afr[fm], bfr[fn]);
    }

    // epilogue: BN + SiLU + store
    int g = lane >> 2, tc4 = lane & 3;
    #pragma unroll
    for (int fm = 0; fm < 4; fm++) {
        int r0 = m_base + 16*fm + g, r1 = r0 + 8;
        float sc0 = g_ep[r0*2], sh0 = g_ep[r0*2+1];
        float sc1 = g_ep[r1*2], sh1 = g_ep[r1*2+1];
        float* o0 = out + ((size_t)b*OUP_ + r0)*P_ + pos0 + n_base + 2*tc4;
        float* o1 = out + ((size_t)b*OUP_ + r1)*P_ + pos0 + n_base + 2*tc4;
        #pragma unroll
        for (int fn = 0; fn < 4; fn++) {
            float z0 = fmaf(acc[fm][fn][0], sc0, sh0);
            float z1 = fmaf(acc[fm][fn][1], sc0, sh0);
            float z2 = fmaf(acc[fm][fn][2], sc1, sh1);
            float z3 = fmaf(acc[fm][fn][3], sc1, sh1);
            float2 v0 = make_float2(z0/(1.f+__expf(-z0)), z1/(1.f+__expf(-z1)));
            float2 v1 = make_float2(z2/(1.f+__expf(-z2)), z3/(1.f+__expf(-z3)));
            *reinterpret_cast<float2*>(o0 + 8*fn) = v0;
            *reinterpret_cast<float2*>(o1 + 8*fn) = v1;
        }
    }
}

extern "C" void kernel_launch(void* const* d_in, const int* in_sizes, int n_in,
                              void* d_out, int out_size)
{
    const float* x      = (const float*)d_in[0];
    const float* gen_w  = (const float*)d_in[1];
    const float* bg     = (const float*)d_in[2];
    const float* bb     = (const float*)d_in[3];
    const float* bm     = (const float*)d_in[4];
    const float* bv     = (const float*)d_in[5];
    const float* gn_w   = (const float*)d_in[6];
    const float* gn_b   = (const float*)d_in[7];
    const float* cw     = (const float*)d_in[8];
    const float* cb     = (const float*)d_in[9];
    const float* sw     = (const float*)d_in[10];
    const float* sb     = (const float*)d_in[11];
    const float* wadd   = (const float*)d_in[12];
    const float* conv_w = (const float*)d_in[13];
    const float* cbg    = (const float*)d_in[14];
    const float* cbb    = (const float*)d_in[15];
    const float* cbm    = (const float*)d_in[16];
    const float* cbv    = (const float*)d_in[17];
    float* out = (float*)d_out;

    cudaFuncSetAttribute(k3_mma, cudaFuncAttributeMaxDynamicSharedMemorySize, K3_DYN);

    k2b_prep<<<(CE_*OUP_ + 255)/256, 256>>>(conv_w, cbg, cbb, cbm, cbv);  // also zeros stats
    k1_gen<<<dim3(8, C_, B_), 256>>>(x, gen_w, bg, bb, bm, bv);
    k2_gate<<<1, 512>>>(gn_w, gn_b, cw, cb, sw, sb, wadd);
    k3_mma<<<dim3(P_/128, B_), 256, K3_DYN>>>(out);
}

// round 16
// speedup vs baseline: 1.3210x; 1.0421x over previous
#include <cuda_runtime.h>
#include <cuda_fp16.h>
#include <cstdint>

#define B_   8
#define C_   64
#define H_   128
#define W_   128
#define CE_  576
#define P_   (H_*W_)
#define OUP_ 128
#define EPSF 1e-5f

typedef unsigned long long ull;

// ---- scratch (device globals; no runtime allocation allowed) ----
__device__ __half g_ah[(size_t)B_*CE_*P_];  // 151 MB: UNGATED relu(bn(dwconv)) fp16 [b][k][p]
__device__ __half g_wh[CE_*OUP_];           // fp16 weights, chunk-major [36][128 o][16 k]
__device__ float g_stats[B_*C_*2];          // sum, sumsq per (b,c)
__device__ float g_ep[OUP_*2];              // conv BN folded: scale, shift per o

#define PK2F(d,a,b)  asm("mov.b64 %0, {%1, %2};" : "=l"(d) : "f"(a), "f"(b))
#define UPK2F(a,b,d) asm("mov.b64 {%0, %1}, %2;" : "=f"(a), "=f"(b) : "l"(d))
#define MUL2(d,a,b)  asm("mul.rn.f32x2 %0, %1, %2;" : "=l"(d) : "l"(a), "l"(b))
#define FMA2(d,a,b,c) asm("fma.rn.f32x2 %0, %1, %2, %3;" : "=l"(d) : "l"(a), "l"(b), "l"(c))

// ---------------- k1: depthwise conv (packed f32x2) + BN + ReLU + fp16 store + stats ----------------
__global__ __launch_bounds__(256) void k1_gen(
    const float* __restrict__ x,  const float* __restrict__ gw,
    const float* __restrict__ bg, const float* __restrict__ bb,
    const float* __restrict__ bm, const float* __restrict__ bv)
{
    int t = threadIdx.x;
    int rowblk = blockIdx.x, c = blockIdx.y, b = blockIdx.z;
    __shared__ float sx[18*130];
    __shared__ __align__(8) float2 swv2[81], ssc2[9], ssh2[9];
    __shared__ float red[16];

    const float* xp = x + (size_t)(b*C_ + c)*P_;
    for (int idx = t; idx < 18*130; idx += 256) {
        int rr = idx / 130, cc = idx - rr*130;
        int gh = rowblk*16 + rr - 1, gwc = cc - 1;
        float v = 0.f;
        if ((unsigned)gh < (unsigned)H_ && (unsigned)gwc < (unsigned)W_)
            v = xp[gh*W_ + gwc];
        sx[idx] = v;
    }
    int ce0 = c*9;
    if (t < 81) {
        float w = gw[ce0*9 + t];
        swv2[t] = make_float2(w, w);
    }
    if (t < 9) {
        float g = bg[ce0+t];
        float sc = g / sqrtf(bv[ce0+t] + EPSF);
        float sh = bb[ce0+t] - bm[ce0+t]*sc;
        ssc2[t] = make_float2(sc, sc);
        ssh2[t] = make_float2(sh, sh);
    }
    __syncthreads();

    int r = t >> 4, c8 = (t & 15) * 8;
    ull P0[9], P1[9], P2[9];
    {
        float xs0[10], xs1[10], xs2[10];
        #pragma unroll
        for (int i = 0; i < 10; i++) {
            xs0[i] = sx[(r  )*130 + c8 + i];
            xs1[i] = sx[(r+1)*130 + c8 + i];
            xs2[i] = sx[(r+2)*130 + c8 + i];
        }
        #pragma unroll
        for (int s = 0; s < 9; s++) {
            PK2F(P0[s], xs0[s], xs0[s+1]);
            PK2F(P1[s], xs1[s], xs1[s+1]);
            PK2F(P2[s], xs2[s], xs2[s+1]);
        }
    }
    float lsum = 0.f, lsq = 0.f;
    int gh0 = rowblk*16 + r;
    #pragma unroll
    for (int j = 0; j < 9; j++) {
        const ull* wj = reinterpret_cast<const ull*>(&swv2[j*9]);
        ull w0=wj[0], w1=wj[1], w2=wj[2], w3=wj[3], w4=wj[4];
        ull w5=wj[5], w6=wj[6], w7=wj[7], w8=wj[8];
        ull scq = *reinterpret_cast<const ull*>(&ssc2[j]);
        ull shq = *reinterpret_cast<const ull*>(&ssh2[j]);
        ull acc2[4];
        #pragma unroll
        for (int p = 0; p < 4; p++) {
            ull a;
            MUL2(a, P0[2*p  ], w0);
            FMA2(a, P0[2*p+1], w1, a);
            FMA2(a, P0[2*p+2], w2, a);
            FMA2(a, P1[2*p  ], w3, a);
            FMA2(a, P1[2*p+1], w4, a);
            FMA2(a, P1[2*p+2], w5, a);
            FMA2(a, P2[2*p  ], w6, a);
            FMA2(a, P2[2*p+1], w7, a);
            FMA2(a, P2[2*p+2], w8, a);
            FMA2(a, a, scq, shq);   // BN
            acc2[p] = a;
        }
        uint4 u;
        unsigned* up = reinterpret_cast<unsigned*>(&u);
        #pragma unroll
        for (int p = 0; p < 4; p++) {
            float v0, v1;
            UPK2F(v0, v1, acc2[p]);
            float a0 = fmaxf(v0, 0.f), a1 = fmaxf(v1, 0.f);
            lsum += a0; lsq = fmaf(a0, a0, lsq);
            lsum += a1; lsq = fmaf(a1, a1, lsq);
            __half2 h = __floats2half2_rn(a0, a1);
            up[p] = *reinterpret_cast<unsigned*>(&h);
        }
        __half* op = g_ah + ((size_t)(b*CE_ + ce0 + j)*H_ + gh0)*W_ + c8;
        *reinterpret_cast<uint4*>(op) = u;
    }
    #pragma unroll
    for (int off = 16; off; off >>= 1) {
        lsum += __shfl_down_sync(0xffffffffu, lsum, off);
        lsq  += __shfl_down_sync(0xffffffffu, lsq , off);
    }
    int wid = t >> 5, lane = t & 31;
    if (lane == 0) { red[wid] = lsum; red[wid+8] = lsq; }
    __syncthreads();
    if (t == 0) {
        float s = 0.f, q = 0.f;
        #pragma unroll
        for (int i = 0; i < 8; i++) { s += red[i]; q += red[i+8]; }
        atomicAdd(&g_stats[(b*C_+c)*2+0], s);
        atomicAdd(&g_stats[(b*C_+c)*2+1], q);
    }
}

// ---------------- k2b: zero stats + W fp16 chunk-major + fold conv BN ----------------
__global__ void k2b_prep(const float* __restrict__ cwv,
                         const float* __restrict__ g, const float* __restrict__ bb,
                         const float* __restrict__ m, const float* __restrict__ v)
{
    int idx = blockIdx.x*256 + threadIdx.x;
    if (idx < CE_*OUP_) {
        int o = idx / CE_, k = idx - o*CE_;
        g_wh[((size_t)(k >> 4)*OUP_ + o)*16 + (k & 15)] = __float2half_rn(cwv[idx]);
    }
    if (blockIdx.x == 0) {
        int i = threadIdx.x;
        g_stats[i] = 0.f; g_stats[i+256] = 0.f;
        g_stats[i+512] = 0.f; g_stats[i+768] = 0.f;
        if (i < OUP_) {
            float sc = g[i] / sqrtf(v[i] + EPSF);
            g_ep[i*2]   = sc;
            g_ep[i*2+1] = bb[i] - m[i]*sc;
        }
    }
}

// fp16 gate transform on 8 packed halves: a * (G0 + G1*tanh(A1*a + B1))
// gp packed as uint4 {A1A1, B1B1, G1G1, G0G0}
static __device__ __forceinline__ uint4 gate8h(uint4 u, uint4 gp) {
    __half2 A1 = *reinterpret_cast<__half2*>(&gp.x);
    __half2 B1 = *reinterpret_cast<__half2*>(&gp.y);
    __half2 G1 = *reinterpret_cast<__half2*>(&gp.z);
    __half2 G0 = *reinterpret_cast<__half2*>(&gp.w);
    __half2* h = reinterpret_cast<__half2*>(&u);
    #pragma unroll
    for (int i = 0; i < 4; i++) {
        __half2 a = h[i];
        __half2 tt = __hfma2(A1, a, B1);
        uint32_t th;
        asm("tanh.approx.f16x2 %0, %1;" : "=r"(th) : "r"(*reinterpret_cast<uint32_t*>(&tt)));
        __half2 g = __hfma2(G1, *reinterpret_cast<__half2*>(&th), G0);
        h[i] = __hmul2(a, g);
    }
    return u;
}

// ---------------- k3: fp16 mma.sync GEMM, 10-stage cp.async, chunk-PAIR iterations, inline gate fold ----------------
#define LDSM4(r0,r1,r2,r3,addr) \
    asm volatile("ldmatrix.sync.aligned.m8n8.x4.shared.b16 {%0,%1,%2,%3}, [%4];" \
        : "=r"(r0),"=r"(r1),"=r"(r2),"=r"(r3) : "r"(addr))
#define LDSM4T(r0,r1,r2,r3,addr) \
    asm volatile("ldmatrix.sync.aligned.m8n8.x4.trans.shared.b16 {%0,%1,%2,%3}, [%4];" \
        : "=r"(r0),"=r"(r1),"=r"(r2),"=r"(r3) : "r"(addr))
#define MMA16816(c, a, b) \
    asm volatile("mma.sync.aligned.m16n8k16.row.col.f32.f16.f16.f32 " \
        "{%0,%1,%2,%3}, {%4,%5,%6,%7}, {%8,%9}, {%0,%1,%2,%3};" \
        : "+f"(c[0]),"+f"(c[1]),"+f"(c[2]),"+f"(c[3]) \
        : "r"(a[0]),"r"(a[1]),"r"(a[2]),"r"(a[3]), "r"(b[0]),"r"(b[1]))
#define CP16(dst, src) \
    asm volatile("cp.async.cg.shared.global [%0], [%1], 16;" :: "r"(dst), "l"(src))
#define CPCOMMIT() asm volatile("cp.async.commit_group;" ::: "memory")
#define CPWAIT2()  asm volatile("cp.async.wait_group 2;" ::: "memory")

static __device__ __forceinline__ uint32_t swoff(int row, int sel) {
    return (uint32_t)(row*32 + ((sel<<4) ^ ((row & 4) << 2)));
}

#define K3_STAGE 8192           // W 4KB + B 4KB per stage (one 16-k chunk)
#define K3_NST   10             // 5 chunk-pairs resident
#define K3_GP    (K3_NST*K3_STAGE)
#define K3_DYN   (K3_GP + 1024)

__global__ __launch_bounds__(256, 2) void k3_mma(
    const float* __restrict__ gn_w, const float* __restrict__ gn_b,
    const float* __restrict__ cw,  const float* __restrict__ cb,
    const float* __restrict__ sw,  const float* __restrict__ sb,
    const float* __restrict__ wadd_p, float* __restrict__ out)
{
    extern __shared__ __align__(16) char dyn[];

    int t = threadIdx.x, lane = t & 31, warp = t >> 5;
    int m_base = (warp >> 2) * 64;
    int n_base = (warp & 3) * 32;
    int b = blockIdx.y, pos0 = blockIdx.x * 128;

    // inline gate fold (was k2_gate): per-channel constants -> packed half2 table
    if (t < 64) {
        int cg = t & 7;
        float s = g_stats[(b*C_+t)*2], q = g_stats[(b*C_+t)*2+1];
        const float N = (float)(9*P_);
        float mean = s / N;
        float var  = fmaxf(q / N - mean*mean, 0.f);
        float inv  = 1.f / sqrtf(var + EPSF);
        float wadd = *wadd_p;
        float tc = cw[cg]*mean + cb[cg];
        float gC = 1.f / (1.f + __expf(-tc));
        float alpha = sw[cg]*gn_w[cg]*inv;
        float beta  = sw[cg]*(gn_b[cg] - mean*inv*gn_w[cg]) + sb[cg];
        float w2 = 1.f - wadd;
        __half2 a1 = __float2half2_rn(0.5f*alpha);
        __half2 b1 = __float2half2_rn(0.5f*beta);
        __half2 g1 = __float2half2_rn(0.5f*w2);
        __half2 g0 = __float2half2_rn(wadd*gC + 0.5f*w2);
        uint4 pk;
        pk.x = *reinterpret_cast<uint32_t*>(&a1);
        pk.y = *reinterpret_cast<uint32_t*>(&b1);
        pk.z = *reinterpret_cast<uint32_t*>(&g1);
        pk.w = *reinterpret_cast<uint32_t*>(&g0);
        reinterpret_cast<uint4*>(dyn + K3_GP)[t] = pk;
    }
    const uint4* gpArr = reinterpret_cast<const uint4*>(dyn + K3_GP);
    const __half* aBase = g_ah + (size_t)b*CE_*P_ + pos0;

    float acc[4][4][4];
    #pragma unroll
    for (int i = 0; i < 4; i++)
        #pragma unroll
        for (int j = 0; j < 4; j++)
            #pragma unroll
            for (int k = 0; k < 4; k++) acc[i][j][k] = 0.f;

    uint32_t stBase = (uint32_t)__cvta_generic_to_shared(dyn);

    uint32_t offA = swoff(m_base + (lane & 15), lane >> 4);
    int gq = lane >> 3, rq = lane & 7;
    int kL = (gq & 1)*8 + rq;
    int cBb = (n_base >> 3) + (gq >> 1);
    // producer offsets
    int kb = t >> 4, chb = t & 15;
    uint32_t bsm = (uint32_t)kb*256 + (uint32_t)(((chb & 8) | ((chb ^ kb) & 7)) << 4);
    int wrow = t >> 1, wsel = t & 1;
    uint32_t wst = swoff(wrow, wsel);
    const __half* wPtr = g_wh + ((size_t)wrow*16) + wsel*8;

    // issue one chunk-pair (2 chunks) as ONE commit group; st0 = (2p)%10
    auto issuePair = [&](int p, int st0) {
        int kc0 = 2*p;
        int st1 = st0 + 1;                       // 2p even, so st0+1 <= 9
        CP16(stBase + st0*K3_STAGE + wst, wPtr + (size_t)kc0*OUP_*16);
        CP16(stBase + st0*K3_STAGE + 4096 + bsm, aBase + (size_t)(kc0*16 + kb)*P_ + chb*8);
        CP16(stBase + st1*K3_STAGE + wst, wPtr + (size_t)(kc0+1)*OUP_*16);
        CP16(stBase + st1*K3_STAGE + 4096 + bsm, aBase + (size_t)((kc0+1)*16 + kb)*P_ + chb*8);
        CPCOMMIT();
    };
    auto gateChunk = [&](int kc, int st) {
        uint4* bp = reinterpret_cast<uint4*>(dyn + st*K3_STAGE + 4096 + bsm);
        *bp = gate8h(*bp, gpArr[(kc*16 + kb) / 9]);
    };
    auto mmaChunk = [&](int st) {
        uint32_t aW = stBase + st*K3_STAGE + offA;
        uint32_t aB2 = stBase + st*K3_STAGE + 4096;
        uint32_t afr[4][4], bfr[4][2];
        #pragma unroll
        for (int fm = 0; fm < 4; fm++)
            LDSM4(afr[fm][0], afr[fm][1], afr[fm][2], afr[fm][3], aW + fm*512);
        #pragma unroll
        for (int pr = 0; pr < 2; pr++) {
            uint32_t r0, r1, r2, r3;
            int cc = cBb + pr*2;
            int s16 = (cc & 8) | ((cc ^ kL) & 7);
            uint32_t off = (uint32_t)kL*256 + (uint32_t)s16*16;
            LDSM4T(r0, r1, r2, r3, aB2 + off);
            bfr[2*pr][0] = r0; bfr[2*pr][1] = r1;
            bfr[2*pr+1][0] = r2; bfr[2*pr+1][1] = r3;
        }
        #pragma unroll
        for (int fm = 0; fm < 4; fm++)
            #pragma unroll
            for (int fn = 0; fn < 4; fn++)
                MMA16816(acc[fm][fn], afr[fm], bfr[fn]);
    };

    issuePair(0, 0); issuePair(1, 2); issuePair(2, 4); issuePair(3, 6);
    CPWAIT2();          // pairs 0,1 landed (own copies visible to this thread)
    __syncthreads();    // gp table published
    gateChunk(0, 0); gateChunk(1, 1);

    int mmaSt = 0, gateSt = 2, issSt = 8;
    for (int p = 0; p < 18; p++) {
        if (p < 17) {
            CPWAIT2();                        // pairs <= p+1 landed
            gateChunk(2*p+2, gateSt);
            gateChunk(2*p+3, gateSt+1);
            gateSt += 2; if (gateSt == K3_NST) gateSt = 0;
        }
        __syncthreads();                      // gates of pair p + drain of pair p-1 reads
        if (p < 14) {
            issuePair(p+4, issSt);
            issSt += 2; if (issSt == K3_NST) issSt = 0;
        } else CPCOMMIT();
        mmaChunk(mmaSt);
        mmaChunk(mmaSt+1);
        mmaSt += 2; if (mmaSt == K3_NST) mmaSt = 0;
    }

    // epilogue: BN + SiLU + store
    int g = lane >> 2, tc4 = lane & 3;
    #pragma unroll
    for (int fm = 0; fm < 4; fm++) {
        int r0 = m_base + 16*fm + g, r1 = r0 + 8;
        float sc0 = g_ep[r0*2], sh0 = g_ep[r0*2+1];
        float sc1 = g_ep[r1*2], sh1 = g_ep[r1*2+1];
        float* o0 = out + ((size_t)b*OUP_ + r0)*P_ + pos0 + n_base + 2*tc4;
        float* o1 = out + ((size_t)b*OUP_ + r1)*P_ + pos0 + n_base + 2*tc4;
        #pragma unroll
        for (int fn = 0; fn < 4; fn++) {
            float z0 = fmaf(acc[fm][fn][0], sc0, sh0);
            float z1 = fmaf(acc[fm][fn][1], sc0, sh0);
            float z2 = fmaf(acc[fm][fn][2], sc1, sh1);
            float z3 = fmaf(acc[fm][fn][3], sc1, sh1);
            float2 v0 = make_float2(z0/(1.f+__expf(-z0)), z1/(1.f+__expf(-z1)));
            float2 v1 = make_float2(z2/(1.f+__expf(-z2)), z3/(1.f+__expf(-z3)));
            *reinterpret_cast<float2*>(o0 + 8*fn) = v0;
            *reinterpret_cast<float2*>(o1 + 8*fn) = v1;
        }
    }
}

extern "C" void kernel_launch(void* const* d_in, const int* in_sizes, int n_in,
                              void* d_out, int out_size)
{
    const float* x      = (const float*)d_in[0];
    const float* gen_w  = (const float*)d_in[1];
    const float* bg     = (const float*)d_in[2];
    const float* bb     = (const float*)d_in[3];
    const float* bm     = (const float*)d_in[4];
    const float* bv     = (const float*)d_in[5];
    const float* gn_w   = (const float*)d_in[6];
    const float* gn_b   = (const float*)d_in[7];
    const float* cw     = (const float*)d_in[8];
    const float* cb     = (const float*)d_in[9];
    const float* sw     = (const float*)d_in[10];
    const float* sb     = (const float*)d_in[11];
    const float* wadd   = (const float*)d_in[12];
    const float* conv_w = (const float*)d_in[13];
    const float* cbg    = (const float*)d_in[14];
    const float* cbb    = (const float*)d_in[15];
    const float* cbm    = (const float*)d_in[16];
    const float* cbv    = (const float*)d_in[17];
    float* out = (float*)d_out;

    cudaFuncSetAttribute(k3_mma, cudaFuncAttributeMaxDynamicSharedMemorySize, K3_DYN);

    k2b_prep<<<(CE_*OUP_ + 255)/256, 256>>>(conv_w, cbg, cbb, cbm, cbv);  // also zeros stats
    k1_gen<<<dim3(8, C_, B_), 256>>>(x, gen_w, bg, bb, bm, bv);
    k3_mma<<<dim3(P_/128, B_), 256, K3_DYN>>>(gn_w, gn_b, cw, cb, sw, sb, wadd, out);
}